// round 13
// baseline (speedup 1.0000x reference)
#include <cuda_runtime.h>
#include <cuda_bf16.h>
#include <stdint.h>

// ============================================================
// Problem dims
// ============================================================
#define IN_F  4096
#define OUT_F 4096
#define BATCH 8192

#define BM 128
#define BN 128
#define BK 32
#define NK (IN_F / BK)          // 128 k-tiles
#define NPM (BATCH / BM)        // 64
#define NPN (OUT_F / BN)        // 32
#define TILE_GROUP 8
#define THREADS 128             // 4 warps: 2 (M) x 2 (N), warp tile 64x64
#define STAGES 3

#define NK8  (IN_F / 8)         // 512 k8 groups per row
#define NK16 (IN_F / 16)        // 256 k16 groups per row

// SMEM: [0..24) full mbar[3], [32..56) empty mbar[3], buffers at 128
#define SM_BUF0 128
#define SM_A_BYTES 16384
#define SM_B_BYTES 16384
#define STAGE_BYTES (SM_A_BYTES + SM_B_BYTES)        // 32768
#define SMEM_TOTAL (SM_BUF0 + STAGES * STAGE_BYTES)  // 98432 -> 2 CTAs/SM

// per-refill global byte advance
#define A_STEP 2048u            // 4 k8 groups * 32 lanes * 16 B
#define B_STEP 1024u            // 2 k16 groups * 32 lanes * 16 B

// fused prep block ranges (256 threads each)
#define PREP_X_BLOCKS 32768
#define PREP_W_BLOCKS 16384
#define PREP_BLOCKS (PREP_X_BLOCKS + PREP_W_BLOCKS + 16)

// ============================================================
// Scratch
// ============================================================
__device__ float4 g_XP[(size_t)(BATCH / 16) * NK8 * 32];
__device__ float4 g_WP[(size_t)(OUT_F / 8) * NK16 * 32];
__device__ float  g_bias[OUT_F];

// ============================================================
// Helpers
// ============================================================
__device__ __forceinline__ float rnd_tf32(float f) {
    float r;
    asm("cvt.rna.tf32.f32 %0, %1;" : "=f"(r) : "f"(f));
    return r;
}

__device__ __forceinline__ uint32_t smem_u32(const void* p) {
    uint32_t a;
    asm("{ .reg .u64 t; cvta.to.shared.u64 t, %1; cvt.u32.u64 %0, t; }"
        : "=r"(a) : "l"(p));
    return a;
}

__device__ __forceinline__ void cp16(uint32_t saddr, const void* gptr) {
    asm volatile("cp.async.cg.shared.global [%0], [%1], 16;\n"
                 :: "r"(saddr), "l"(gptr));
}

__device__ __forceinline__ void mbar_init(uint32_t a, uint32_t cnt) {
    asm volatile("mbarrier.init.shared.b64 [%0], %1;" :: "r"(a), "r"(cnt) : "memory");
}
__device__ __forceinline__ void mbar_arrive(uint32_t a) {
    asm volatile("mbarrier.arrive.shared.b64 _, [%0];" :: "r"(a) : "memory");
}
__device__ __forceinline__ void mbar_wait(uint32_t addr, uint32_t parity) {
    asm volatile(
        "{\n\t.reg .pred P;\n\t"
        "WAIT_%=:\n\t"
        "mbarrier.try_wait.parity.acquire.cta.shared::cta.b64 P, [%0], %1, 0x989680;\n\t"
        "@P bra.uni DONE_%=;\n\t"
        "bra.uni WAIT_%=;\n\t"
        "DONE_%=:\n\t}"
        :: "r"(addr), "r"(parity) : "memory");
}
__device__ __forceinline__ void cp_async_arrive(uint32_t a) {
    asm volatile("cp.async.mbarrier.arrive.noinc.shared.b64 [%0];"
                 :: "r"(a) : "memory");
}

__device__ __forceinline__ void mma_tf32(float& c0, float& c1, float& c2, float& c3,
                                         uint32_t a0, uint32_t a1, uint32_t a2, uint32_t a3,
                                         uint32_t b0, uint32_t b1) {
    asm volatile(
        "mma.sync.aligned.m16n8k8.row.col.f32.tf32.tf32.f32 "
        "{%0,%1,%2,%3}, {%4,%5,%6,%7}, {%8,%9}, {%0,%1,%2,%3};"
        : "+f"(c0), "+f"(c1), "+f"(c2), "+f"(c3)
        : "r"(a0), "r"(a1), "r"(a2), "r"(a3), "r"(b0), "r"(b1));
}

// ============================================================
// Fused prep: X pack | W materialize+pack | bias, by block range
// ============================================================
__global__ void prep_fused(const float* __restrict__ x,
                           const float* __restrict__ mu,
                           const float* __restrict__ lv,
                           const float* __restrict__ eps,
                           const float* __restrict__ bmu,
                           const float* __restrict__ blv,
                           const float* __restrict__ beps) {
    int bid = blockIdx.x;
    if (bid < PREP_X_BLOCKS) {
        size_t i = (size_t)bid * 256 + threadIdx.x;          // 8388608
        int row16 = (int)(i >> 14);
        int rem   = (int)(i & 16383);
        int k8    = rem >> 5;
        int lane  = rem & 31;
        int g = lane >> 2, t = lane & 3;
        const float* p0 = x + (size_t)(row16 * 16 + g) * IN_F + k8 * 8 + t;
        float4 v;
        v.x = rnd_tf32(p0[0]);
        v.y = rnd_tf32(p0[8 * IN_F]);
        v.z = rnd_tf32(p0[4]);
        v.w = rnd_tf32(p0[8 * IN_F + 4]);
        g_XP[i] = v;
    } else if (bid < PREP_X_BLOCKS + PREP_W_BLOCKS) {
        size_t i = (size_t)(bid - PREP_X_BLOCKS) * 256 + threadIdx.x;  // 4194304
        int col8 = (int)(i >> 13);
        int rem  = (int)(i & 8191);
        int k16  = rem >> 5;
        int lane = rem & 31;
        int g = lane >> 2, t = lane & 3;
        size_t base = (size_t)(col8 * 8 + g) * IN_F + k16 * 16 + t;
        float4 v;
#pragma unroll
        for (int j = 0; j < 4; ++j) {
            size_t a = base + (j & 1) * 4 + (j >> 1) * 8;
            float w = mu[a] + eps[a] * __expf(0.5f * lv[a]);
            (&v.x)[j] = rnd_tf32(w);
        }
        g_WP[i] = v;
    } else {
        int i = (bid - PREP_X_BLOCKS - PREP_W_BLOCKS) * 256 + threadIdx.x;
        if (i < OUT_F) g_bias[i] = bmu[i] + beps[i] * __expf(0.5f * blv[i]);
    }
}

// ============================================================
// GEMM: C[128,128] per CTA, 128 threads (4 warps = 2 x 2),
// warp tile 64 x 64, BK=32, 3-stage ring, refill 1 ahead
// (empty-wait reaches back to kt-2 => drift window 2).
// 2 CTAs per SM: independent CTAs cover each other's stalls.
// ============================================================
__global__ void __launch_bounds__(THREADS, 2) gemm_kernel(float* __restrict__ out) {
    extern __shared__ char smem[];
    const uint32_t sb = smem_u32(smem);
    const int tid = threadIdx.x;
    const int wid = tid >> 5;
    const int lane = tid & 31;
    const int wm = wid >> 1;      // 0..1  (M, 64 rows)
    const int wn = wid & 1;       // 0..1  (N, 64 cols)
    const int gq = lane >> 2;
    const int tg = lane & 3;

    int pid = blockIdx.x;
    int grp = pid / (TILE_GROUP * NPN);
    int pin = pid % (TILE_GROUP * NPN);
    int pm  = grp * TILE_GROUP + (pin % TILE_GROUP);
    int pn  = pin / TILE_GROUP;
    const int m0 = pm * BM;
    const int n0 = pn * BN;
    const int m016 = m0 >> 4;
    const int n08  = n0 >> 3;

    // full[s] at sb + s*8, empty[s] at sb + 32 + s*8
    if (tid == 0) {
#pragma unroll
        for (int s = 0; s < STAGES; ++s) {
            mbar_init(sb + s * 8, 128);
            mbar_init(sb + 32 + s * 8, 4);
        }
    }
    __syncthreads();

    // ---- strength-reduced refill offsets ----
    uint32_t offA[8], offB[8];
#pragma unroll
    for (int t = 0; t < 8; ++t) {
        int ca = tid + t * THREADS;           // 0..1023
        int r16l = ca >> 7;                   // 128 chunks per row16 group
        int inner = ca & 127;
        offA[t] = (uint32_t)(((((m016 + r16l) * NK8) + (inner >> 5)) * 32
                              + (inner & 31)) * 16);
    }
#pragma unroll
    for (int t = 0; t < 8; ++t) {
        int cb = tid + t * THREADS;           // 0..1023
        int c8l = cb >> 6;                    // 64 chunks per col8 group
        int inner = cb & 63;
        offB[t] = (uint32_t)(((((n08 + c8l) * NK16) + (inner >> 5)) * 32
                              + (inner & 31)) * 16);
    }
    const char* gXb = (const char*)g_XP;
    const char* gWb = (const char*)g_WP;

    auto load_A = [&](uint32_t abase) {
#pragma unroll
        for (int t = 0; t < 8; ++t)
            cp16(abase + (uint32_t)(tid + t * THREADS) * 16u, gXb + offA[t]);
#pragma unroll
        for (int t = 0; t < 8; ++t) offA[t] += A_STEP;
    };
    auto load_B = [&](uint32_t bbase) {
#pragma unroll
        for (int t = 0; t < 8; ++t)
            cp16(bbase + (uint32_t)(tid + t * THREADS) * 16u, gWb + offB[t]);
#pragma unroll
        for (int t = 0; t < 8; ++t) offB[t] += B_STEP;
    };

    // prologue: load stage 0 (kt=0); kt+1 loads happen in-loop
    load_A(sb + SM_BUF0);
    load_B(sb + SM_BUF0 + SM_A_BYTES);
    cp_async_arrive(sb + 0);

    float c[4][8][4];
#pragma unroll
    for (int mt = 0; mt < 4; ++mt)
#pragma unroll
        for (int nt = 0; nt < 8; ++nt)
#pragma unroll
            for (int j = 0; j < 4; ++j) c[mt][nt][j] = 0.0f;

    // cursors: consumer full (cfs,cfp); producer stage pfs (= (kt+1)%3);
    // empty-wait parity cursor (ec3,ep) pre-wound so ep is valid from kt=2
    int cfs = 0; uint32_t cfp = 0;
    int pfs = 1;
    int ec3 = 1; uint32_t ep = 1;

    for (int kt = 0; kt < NK; ++kt) {
        mbar_wait(sb + cfs * 8, cfp);                 // full[cfs]

        const uint32_t sbase = sb + SM_BUF0 + (uint32_t)(cfs * STAGE_BYTES);
        const float4* sA = reinterpret_cast<const float4*>(
            smem + (sbase - sb));
        const float4* sB = reinterpret_cast<const float4*>(
            smem + (sbase - sb) + SM_A_BYTES);

        const bool more = (kt + 1 < NK);
        const uint32_t pbase = sb + SM_BUF0 + (uint32_t)(pfs * STAGE_BYTES);

#pragma unroll
        for (int k16 = 0; k16 < 2; ++k16) {
            float4 af[4];
#pragma unroll
            for (int mt = 0; mt < 4; ++mt)
                af[mt] = sA[(((wm * 4 + mt) * 4 + k16 * 2) * 32) + lane];
            float4 bf[8];
#pragma unroll
            for (int nt = 0; nt < 8; ++nt) {
                bf[nt] = sB[(((wn * 8 + nt) * 2 + k16) * 32) + lane];
                uint32_t b0 = __float_as_uint(bf[nt].x);
                uint32_t b1 = __float_as_uint(bf[nt].y);
#pragma unroll
                for (int mt = 0; mt < 4; ++mt) {
                    mma_tf32(c[mt][nt][0], c[mt][nt][1],
                             c[mt][nt][2], c[mt][nt][3],
                             __float_as_uint(af[mt].x), __float_as_uint(af[mt].y),
                             __float_as_uint(af[mt].z), __float_as_uint(af[mt].w),
                             b0, b1);
                }
            }
#pragma unroll
            for (int mt = 0; mt < 4; ++mt)
                af[mt] = sA[(((wm * 4 + mt) * 4 + k16 * 2 + 1) * 32) + lane];
#pragma unroll
            for (int nt = 0; nt < 8; ++nt) {
                uint32_t b0 = __float_as_uint(bf[nt].z);
                uint32_t b1 = __float_as_uint(bf[nt].w);
#pragma unroll
                for (int mt = 0; mt < 4; ++mt) {
                    mma_tf32(c[mt][nt][0], c[mt][nt][1],
                             c[mt][nt][2], c[mt][nt][3],
                             __float_as_uint(af[mt].x), __float_as_uint(af[mt].y),
                             __float_as_uint(af[mt].z), __float_as_uint(af[mt].w),
                             b0, b1);
                }
            }
            // interleaved refill for kt+1 into stage pfs
            if (k16 == 0 && more) {
                if (kt >= 2)
                    mbar_wait(sb + 32 + pfs * 8, ep);   // empty[pfs] (read at kt-2)
                load_A(pbase);
            }
            if (k16 == 1 && more) {
                load_B(pbase + SM_A_BYTES);
                cp_async_arrive(sb + pfs * 8);          // full[pfs]
            }
        }

        // this warp finished all reads of stage cfs
        if (lane == 0) mbar_arrive(sb + 32 + cfs * 8);  // empty[cfs]

        // advance cursors
        if (++cfs == 3) { cfs = 0; cfp ^= 1u; }
        if (++pfs == 3) { pfs = 0; }
        if (++ec3 == 3) { ec3 = 0; ep ^= 1u; }
    }

    // ---- epilogue: bias + store ----
#pragma unroll
    for (int mt = 0; mt < 4; ++mt) {
        const int row0 = m0 + wm * 64 + mt * 16 + gq;
#pragma unroll
        for (int nt = 0; nt < 8; ++nt) {
            const int col = n0 + wn * 64 + nt * 8 + 2 * tg;
            const float2 bv = *reinterpret_cast<const float2*>(g_bias + col);
            float2 v0, v1;
            v0.x = c[mt][nt][0] + bv.x;
            v0.y = c[mt][nt][1] + bv.y;
            v1.x = c[mt][nt][2] + bv.x;
            v1.y = c[mt][nt][3] + bv.y;
            *reinterpret_cast<float2*>(out + (size_t)row0 * OUT_F + col) = v0;
            *reinterpret_cast<float2*>(out + (size_t)(row0 + 8) * OUT_F + col) = v1;
        }
    }
}

// ============================================================
// Launch
// ============================================================
extern "C" void kernel_launch(void* const* d_in, const int* in_sizes, int n_in,
                              void* d_out, int out_size) {
    const float* x    = (const float*)d_in[0];
    const float* wmu  = (const float*)d_in[1];
    const float* wlv  = (const float*)d_in[2];
    const float* bmu  = (const float*)d_in[3];
    const float* blv  = (const float*)d_in[4];
    const float* weps = (const float*)d_in[5];
    const float* beps = (const float*)d_in[6];
    float* out = (float*)d_out;

    prep_fused<<<PREP_BLOCKS, 256>>>(x, wmu, wlv, weps, bmu, blv, beps);

    cudaFuncSetAttribute(gemm_kernel,
                         cudaFuncAttributeMaxDynamicSharedMemorySize, SMEM_TOTAL);
    gemm_kernel<<<NPM * NPN, THREADS, SMEM_TOTAL>>>(out);
}

// round 14
// speedup vs baseline: 1.2859x; 1.2859x over previous
#include <cuda_runtime.h>
#include <cuda_bf16.h>
#include <stdint.h>

// ============================================================
// Problem dims
// ============================================================
#define IN_F  4096
#define OUT_F 4096
#define BATCH 8192

#define BM 128
#define BN 128
#define BK 32
#define NK (IN_F / BK)          // 128 k-tiles
#define NPM (BATCH / BM)        // 64
#define NPN (OUT_F / BN)        // 32
#define TILE_GROUP 8
#define THREADS 128             // 4 warps: 2 (M) x 2 (N), warp tile 64x64
#define STAGES 3

#define NK8  (IN_F / 8)         // 512 k8 groups per row
#define NK16 (IN_F / 16)        // 256 k16 groups per row

// SMEM: [0..24) full mbar[3], [32..56) empty mbar[3], buffers at 128
#define SM_BUF0 128
#define SM_A_BYTES 16384
#define SM_B_BYTES 16384
#define STAGE_BYTES (SM_A_BYTES + SM_B_BYTES)        // 32768
#define SMEM_TOTAL (SM_BUF0 + STAGES * STAGE_BYTES)  // 98432 -> 2 CTAs/SM

// per-refill global byte advance
#define A_STEP 2048u
#define B_STEP 1024u

// fused prep block ranges (256 threads each)
#define PREP_X_BLOCKS 32768
#define PREP_W_BLOCKS 16384
#define PREP_BLOCKS (PREP_X_BLOCKS + PREP_W_BLOCKS + 16)

// ============================================================
// Scratch
// ============================================================
__device__ float4 g_XP[(size_t)(BATCH / 16) * NK8 * 32];
__device__ float4 g_WP[(size_t)(OUT_F / 8) * NK16 * 32];
__device__ float  g_bias[OUT_F];

// ============================================================
// Helpers
// ============================================================
__device__ __forceinline__ float rnd_tf32(float f) {
    float r;
    asm("cvt.rna.tf32.f32 %0, %1;" : "=f"(r) : "f"(f));
    return r;
}

__device__ __forceinline__ uint32_t smem_u32(const void* p) {
    uint32_t a;
    asm("{ .reg .u64 t; cvta.to.shared.u64 t, %1; cvt.u32.u64 %0, t; }"
        : "=r"(a) : "l"(p));
    return a;
}

__device__ __forceinline__ void cp16(uint32_t saddr, const void* gptr) {
    asm volatile("cp.async.cg.shared.global [%0], [%1], 16;\n"
                 :: "r"(saddr), "l"(gptr));
}

__device__ __forceinline__ void mbar_init(uint32_t a, uint32_t cnt) {
    asm volatile("mbarrier.init.shared.b64 [%0], %1;" :: "r"(a), "r"(cnt) : "memory");
}
__device__ __forceinline__ void mbar_arrive(uint32_t a) {
    asm volatile("mbarrier.arrive.shared.b64 _, [%0];" :: "r"(a) : "memory");
}
__device__ __forceinline__ void mbar_wait(uint32_t addr, uint32_t parity) {
    asm volatile(
        "{\n\t.reg .pred P;\n\t"
        "WAIT_%=:\n\t"
        "mbarrier.try_wait.parity.acquire.cta.shared::cta.b64 P, [%0], %1, 0x989680;\n\t"
        "@P bra.uni DONE_%=;\n\t"
        "bra.uni WAIT_%=;\n\t"
        "DONE_%=:\n\t}"
        :: "r"(addr), "r"(parity) : "memory");
}
__device__ __forceinline__ void cp_async_arrive(uint32_t a) {
    asm volatile("cp.async.mbarrier.arrive.noinc.shared.b64 [%0];"
                 :: "r"(a) : "memory");
}

__device__ __forceinline__ void mma_tf32(float& c0, float& c1, float& c2, float& c3,
                                         uint32_t a0, uint32_t a1, uint32_t a2, uint32_t a3,
                                         uint32_t b0, uint32_t b1) {
    asm volatile(
        "mma.sync.aligned.m16n8k8.row.col.f32.tf32.tf32.f32 "
        "{%0,%1,%2,%3}, {%4,%5,%6,%7}, {%8,%9}, {%0,%1,%2,%3};"
        : "+f"(c0), "+f"(c1), "+f"(c2), "+f"(c3)
        : "r"(a0), "r"(a1), "r"(a2), "r"(a3), "r"(b0), "r"(b1));
}

// ============================================================
// Fused prep: X pack | W materialize+pack | bias, by block range
// ============================================================
__global__ void prep_fused(const float* __restrict__ x,
                           const float* __restrict__ mu,
                           const float* __restrict__ lv,
                           const float* __restrict__ eps,
                           const float* __restrict__ bmu,
                           const float* __restrict__ blv,
                           const float* __restrict__ beps) {
    int bid = blockIdx.x;
    if (bid < PREP_X_BLOCKS) {
        size_t i = (size_t)bid * 256 + threadIdx.x;          // 8388608
        int row16 = (int)(i >> 14);
        int rem   = (int)(i & 16383);
        int k8    = rem >> 5;
        int lane  = rem & 31;
        int g = lane >> 2, t = lane & 3;
        const float* p0 = x + (size_t)(row16 * 16 + g) * IN_F + k8 * 8 + t;
        float4 v;
        v.x = rnd_tf32(p0[0]);
        v.y = rnd_tf32(p0[8 * IN_F]);
        v.z = rnd_tf32(p0[4]);
        v.w = rnd_tf32(p0[8 * IN_F + 4]);
        g_XP[i] = v;
    } else if (bid < PREP_X_BLOCKS + PREP_W_BLOCKS) {
        size_t i = (size_t)(bid - PREP_X_BLOCKS) * 256 + threadIdx.x;  // 4194304
        int col8 = (int)(i >> 13);
        int rem  = (int)(i & 8191);
        int k16  = rem >> 5;
        int lane = rem & 31;
        int g = lane >> 2, t = lane & 3;
        size_t base = (size_t)(col8 * 8 + g) * IN_F + k16 * 16 + t;
        float4 v;
#pragma unroll
        for (int j = 0; j < 4; ++j) {
            size_t a = base + (j & 1) * 4 + (j >> 1) * 8;
            float w = mu[a] + eps[a] * __expf(0.5f * lv[a]);
            (&v.x)[j] = rnd_tf32(w);
        }
        g_WP[i] = v;
    } else {
        int i = (bid - PREP_X_BLOCKS - PREP_W_BLOCKS) * 256 + threadIdx.x;
        if (i < OUT_F) g_bias[i] = bmu[i] + beps[i] * __expf(0.5f * blv[i]);
    }
}

// ============================================================
// GEMM: C[128,128] per CTA, 128 threads (4 warps = 2 x 2),
// warp tile 64 x 64, BK=32, 3-stage ring, refill 2 AHEAD
// (lead ~1.5 k-tiles for DRAM; empty-wait reaches kt-1).
// 2 CTAs per SM cover each other's stalls.
// ============================================================
__global__ void __launch_bounds__(THREADS, 2) gemm_kernel(float* __restrict__ out) {
    extern __shared__ char smem[];
    const uint32_t sb = smem_u32(smem);
    const int tid = threadIdx.x;
    const int wid = tid >> 5;
    const int lane = tid & 31;
    const int wm = wid >> 1;      // 0..1  (M, 64 rows)
    const int wn = wid & 1;       // 0..1  (N, 64 cols)
    const int gq = lane >> 2;
    const int tg = lane & 3;

    int pid = blockIdx.x;
    int grp = pid / (TILE_GROUP * NPN);
    int pin = pid % (TILE_GROUP * NPN);
    int pm  = grp * TILE_GROUP + (pin % TILE_GROUP);
    int pn  = pin / TILE_GROUP;
    const int m0 = pm * BM;
    const int n0 = pn * BN;
    const int m016 = m0 >> 4;
    const int n08  = n0 >> 3;

    // full[s] at sb + s*8, empty[s] at sb + 32 + s*8
    if (tid == 0) {
#pragma unroll
        for (int s = 0; s < STAGES; ++s) {
            mbar_init(sb + s * 8, 128);
            mbar_init(sb + 32 + s * 8, 4);
        }
    }
    __syncthreads();

    // ---- strength-reduced refill offsets ----
    uint32_t offA[8], offB[8];
#pragma unroll
    for (int t = 0; t < 8; ++t) {
        int ca = tid + t * THREADS;
        int r16l = ca >> 7;
        int inner = ca & 127;
        offA[t] = (uint32_t)(((((m016 + r16l) * NK8) + (inner >> 5)) * 32
                              + (inner & 31)) * 16);
    }
#pragma unroll
    for (int t = 0; t < 8; ++t) {
        int cb = tid + t * THREADS;
        int c8l = cb >> 6;
        int inner = cb & 63;
        offB[t] = (uint32_t)(((((n08 + c8l) * NK16) + (inner >> 5)) * 32
                              + (inner & 31)) * 16);
    }
    const char* gXb = (const char*)g_XP;
    const char* gWb = (const char*)g_WP;

    auto load_A = [&](uint32_t abase) {
#pragma unroll
        for (int t = 0; t < 8; ++t)
            cp16(abase + (uint32_t)(tid + t * THREADS) * 16u, gXb + offA[t]);
#pragma unroll
        for (int t = 0; t < 8; ++t) offA[t] += A_STEP;
    };
    auto load_B = [&](uint32_t bbase) {
#pragma unroll
        for (int t = 0; t < 8; ++t)
            cp16(bbase + (uint32_t)(tid + t * THREADS) * 16u, gWb + offB[t]);
#pragma unroll
        for (int t = 0; t < 8; ++t) offB[t] += B_STEP;
    };

    // prologue: load stages 0 and 1 (kt=0,1); in-loop refills start at kt+2
    load_A(sb + SM_BUF0);
    load_B(sb + SM_BUF0 + SM_A_BYTES);
    cp_async_arrive(sb + 0);
    load_A(sb + SM_BUF0 + STAGE_BYTES);
    load_B(sb + SM_BUF0 + STAGE_BYTES + SM_A_BYTES);
    cp_async_arrive(sb + 8);

    float c[4][8][4];
#pragma unroll
    for (int mt = 0; mt < 4; ++mt)
#pragma unroll
        for (int nt = 0; nt < 8; ++nt)
#pragma unroll
            for (int j = 0; j < 4; ++j) c[mt][nt][j] = 0.0f;

    // cursors:
    //  consumer: cfs = kt%3, cfp = (kt/3)&1
    //  producer: pfs = (kt+2)%3 (starts 2)
    //  empty-wait (for stage pfs, read at kt-1): ep = ((kt-1)/3)&1, used kt>=1
    int cfs = 0; uint32_t cfp = 0;
    int pfs = 2;
    int ec = 0;  uint32_t ep = 0;

    for (int kt = 0; kt < NK; ++kt) {
        mbar_wait(sb + cfs * 8, cfp);                 // full[cfs]

        const float4* sA = reinterpret_cast<const float4*>(
            smem + SM_BUF0 + (size_t)(cfs * STAGE_BYTES));
        const float4* sB = reinterpret_cast<const float4*>(
            smem + SM_BUF0 + (size_t)(cfs * STAGE_BYTES) + SM_A_BYTES);

        const bool more2 = (kt + 2 < NK);
        const uint32_t pbase = sb + SM_BUF0 + (uint32_t)(pfs * STAGE_BYTES);

#pragma unroll
        for (int k16 = 0; k16 < 2; ++k16) {
            float4 af[4];
#pragma unroll
            for (int mt = 0; mt < 4; ++mt)
                af[mt] = sA[(((wm * 4 + mt) * 4 + k16 * 2) * 32) + lane];
            float4 bf[8];
#pragma unroll
            for (int nt = 0; nt < 8; ++nt) {
                bf[nt] = sB[(((wn * 8 + nt) * 2 + k16) * 32) + lane];
                uint32_t b0 = __float_as_uint(bf[nt].x);
                uint32_t b1 = __float_as_uint(bf[nt].y);
#pragma unroll
                for (int mt = 0; mt < 4; ++mt) {
                    mma_tf32(c[mt][nt][0], c[mt][nt][1],
                             c[mt][nt][2], c[mt][nt][3],
                             __float_as_uint(af[mt].x), __float_as_uint(af[mt].y),
                             __float_as_uint(af[mt].z), __float_as_uint(af[mt].w),
                             b0, b1);
                }
            }
#pragma unroll
            for (int mt = 0; mt < 4; ++mt)
                af[mt] = sA[(((wm * 4 + mt) * 4 + k16 * 2 + 1) * 32) + lane];
#pragma unroll
            for (int nt = 0; nt < 8; ++nt) {
                uint32_t b0 = __float_as_uint(bf[nt].z);
                uint32_t b1 = __float_as_uint(bf[nt].w);
#pragma unroll
                for (int mt = 0; mt < 4; ++mt) {
                    mma_tf32(c[mt][nt][0], c[mt][nt][1],
                             c[mt][nt][2], c[mt][nt][3],
                             __float_as_uint(af[mt].x), __float_as_uint(af[mt].y),
                             __float_as_uint(af[mt].z), __float_as_uint(af[mt].w),
                             b0, b1);
                }
            }
            // interleaved refill for kt+2 into stage pfs
            if (k16 == 0 && more2) {
                if (kt >= 1)
                    mbar_wait(sb + 32 + pfs * 8, ep);   // empty[pfs] (read at kt-1)
                load_A(pbase);
            }
            if (k16 == 1 && more2) {
                load_B(pbase + SM_A_BYTES);
                cp_async_arrive(sb + pfs * 8);          // full[pfs]
            }
        }

        // this warp finished all reads of stage cfs
        if (lane == 0) mbar_arrive(sb + 32 + cfs * 8);  // empty[cfs]

        // advance cursors
        if (++cfs == 3) { cfs = 0; cfp ^= 1u; }
        if (++pfs == 3) { pfs = 0; }
        if (kt >= 1) { if (++ec == 3) { ec = 0; ep ^= 1u; } }
    }

    // ---- epilogue: bias + store ----
#pragma unroll
    for (int mt = 0; mt < 4; ++mt) {
        const int row0 = m0 + wm * 64 + mt * 16 + gq;
#pragma unroll
        for (int nt = 0; nt < 8; ++nt) {
            const int col = n0 + wn * 64 + nt * 8 + 2 * tg;
            const float2 bv = *reinterpret_cast<const float2*>(g_bias + col);
            float2 v0, v1;
            v0.x = c[mt][nt][0] + bv.x;
            v0.y = c[mt][nt][1] + bv.y;
            v1.x = c[mt][nt][2] + bv.x;
            v1.y = c[mt][nt][3] + bv.y;
            *reinterpret_cast<float2*>(out + (size_t)row0 * OUT_F + col) = v0;
            *reinterpret_cast<float2*>(out + (size_t)(row0 + 8) * OUT_F + col) = v1;
        }
    }
}

// ============================================================
// Launch
// ============================================================
extern "C" void kernel_launch(void* const* d_in, const int* in_sizes, int n_in,
                              void* d_out, int out_size) {
    const float* x    = (const float*)d_in[0];
    const float* wmu  = (const float*)d_in[1];
    const float* wlv  = (const float*)d_in[2];
    const float* bmu  = (const float*)d_in[3];
    const float* blv  = (const float*)d_in[4];
    const float* weps = (const float*)d_in[5];
    const float* beps = (const float*)d_in[6];
    float* out = (float*)d_out;

    prep_fused<<<PREP_BLOCKS, 256>>>(x, wmu, wlv, weps, bmu, blv, beps);

    cudaFuncSetAttribute(gemm_kernel,
                         cudaFuncAttributeMaxDynamicSharedMemorySize, SMEM_TOTAL);
    gemm_kernel<<<NPM * NPN, THREADS, SMEM_TOTAL>>>(out);
}

// round 15
// speedup vs baseline: 1.3181x; 1.0250x over previous
#include <cuda_runtime.h>
#include <cuda_bf16.h>
#include <stdint.h>

// ============================================================
// Problem dims
// ============================================================
#define IN_F  4096
#define OUT_F 4096
#define BATCH 8192

#define BM 256
#define BN 128
#define BK 32
#define NK (IN_F / BK)          // 128 k-tiles
#define NPM (BATCH / BM)        // 32
#define NPN (OUT_F / BN)        // 32
#define TILE_GROUP 8
#define THREADS 256             // 8 warps: 4 (M) x 2 (N), warp tile 64x64
#define STAGES 4

#define NK8  (IN_F / 8)         // 512 k8 groups per row
#define NK16 (IN_F / 16)        // 256 k16 groups per row

// SMEM: [0..32) full mbar[4], [64..80) read-done flags[4], buffers at 128
#define SM_BUF0 128
#define SM_A_BYTES 32768
#define SM_B_BYTES 16384
#define STAGE_BYTES (SM_A_BYTES + SM_B_BYTES)        // 49152
#define SMEM_TOTAL (SM_BUF0 + STAGES * STAGE_BYTES)  // 196736

// per-refill global byte advance
#define A_STEP 2048u
#define B_STEP 1024u

// fused prep block ranges (256 threads each)
#define PREP_X_BLOCKS 32768
#define PREP_W_BLOCKS 16384
#define PREP_BLOCKS (PREP_X_BLOCKS + PREP_W_BLOCKS + 16)

// ============================================================
// Scratch
// ============================================================
__device__ float4 g_XP[(size_t)(BATCH / 16) * NK8 * 32];
__device__ float4 g_WP[(size_t)(OUT_F / 8) * NK16 * 32];
__device__ float  g_bias[OUT_F];

// ============================================================
// Helpers
// ============================================================
__device__ __forceinline__ float rnd_tf32(float f) {
    float r;
    asm("cvt.rna.tf32.f32 %0, %1;" : "=f"(r) : "f"(f));
    return r;
}

__device__ __forceinline__ uint32_t smem_u32(const void* p) {
    uint32_t a;
    asm("{ .reg .u64 t; cvta.to.shared.u64 t, %1; cvt.u32.u64 %0, t; }"
        : "=r"(a) : "l"(p));
    return a;
}

__device__ __forceinline__ void cp16(uint32_t saddr, const void* gptr) {
    asm volatile("cp.async.cg.shared.global [%0], [%1], 16;\n"
                 :: "r"(saddr), "l"(gptr));
}

__device__ __forceinline__ void mbar_init(uint32_t a, uint32_t cnt) {
    asm volatile("mbarrier.init.shared.b64 [%0], %1;" :: "r"(a), "r"(cnt) : "memory");
}
__device__ __forceinline__ void mbar_wait(uint32_t addr, uint32_t parity) {
    asm volatile(
        "{\n\t.reg .pred P;\n\t"
        "WAIT_%=:\n\t"
        "mbarrier.try_wait.parity.acquire.cta.shared::cta.b64 P, [%0], %1, 0x989680;\n\t"
        "@P bra.uni DONE_%=;\n\t"
        "bra.uni WAIT_%=;\n\t"
        "DONE_%=:\n\t}"
        :: "r"(addr), "r"(parity) : "memory");
}
__device__ __forceinline__ void cp_async_arrive(uint32_t a) {
    asm volatile("cp.async.mbarrier.arrive.noinc.shared.b64 [%0];"
                 :: "r"(a) : "memory");
}

// read-done flags: release-add by reader warps, acquire-spin by refiller
__device__ __forceinline__ void flag_add(uint32_t addr) {
    asm volatile("red.release.cta.shared.add.u32 [%0], %1;"
                 :: "r"(addr), "r"(1u) : "memory");
}
__device__ __forceinline__ void flag_wait(uint32_t addr, uint32_t target) {
    uint32_t v;
    do {
        asm volatile("ld.acquire.cta.shared.u32 %0, [%1];"
                     : "=r"(v) : "r"(addr) : "memory");
    } while ((int)(v - target) < 0);
}

__device__ __forceinline__ void mma_tf32(float& c0, float& c1, float& c2, float& c3,
                                         uint32_t a0, uint32_t a1, uint32_t a2, uint32_t a3,
                                         uint32_t b0, uint32_t b1) {
    asm volatile(
        "mma.sync.aligned.m16n8k8.row.col.f32.tf32.tf32.f32 "
        "{%0,%1,%2,%3}, {%4,%5,%6,%7}, {%8,%9}, {%0,%1,%2,%3};"
        : "+f"(c0), "+f"(c1), "+f"(c2), "+f"(c3)
        : "r"(a0), "r"(a1), "r"(a2), "r"(a3), "r"(b0), "r"(b1));
}

// ============================================================
// Fused prep: X pack | W materialize+pack | bias, by block range
// ============================================================
__global__ void prep_fused(const float* __restrict__ x,
                           const float* __restrict__ mu,
                           const float* __restrict__ lv,
                           const float* __restrict__ eps,
                           const float* __restrict__ bmu,
                           const float* __restrict__ blv,
                           const float* __restrict__ beps) {
    int bid = blockIdx.x;
    if (bid < PREP_X_BLOCKS) {
        size_t i = (size_t)bid * 256 + threadIdx.x;          // 8388608
        int row16 = (int)(i >> 14);
        int rem   = (int)(i & 16383);
        int k8    = rem >> 5;
        int lane  = rem & 31;
        int g = lane >> 2, t = lane & 3;
        const float* p0 = x + (size_t)(row16 * 16 + g) * IN_F + k8 * 8 + t;
        float4 v;
        v.x = rnd_tf32(p0[0]);
        v.y = rnd_tf32(p0[8 * IN_F]);
        v.z = rnd_tf32(p0[4]);
        v.w = rnd_tf32(p0[8 * IN_F + 4]);
        g_XP[i] = v;
    } else if (bid < PREP_X_BLOCKS + PREP_W_BLOCKS) {
        size_t i = (size_t)(bid - PREP_X_BLOCKS) * 256 + threadIdx.x;  // 4194304
        int col8 = (int)(i >> 13);
        int rem  = (int)(i & 8191);
        int k16  = rem >> 5;
        int lane = rem & 31;
        int g = lane >> 2, t = lane & 3;
        size_t base = (size_t)(col8 * 8 + g) * IN_F + k16 * 16 + t;
        float4 v;
#pragma unroll
        for (int j = 0; j < 4; ++j) {
            size_t a = base + (j & 1) * 4 + (j >> 1) * 8;
            float w = mu[a] + eps[a] * __expf(0.5f * lv[a]);
            (&v.x)[j] = rnd_tf32(w);
        }
        g_WP[i] = v;
    } else {
        int i = (bid - PREP_X_BLOCKS - PREP_W_BLOCKS) * 256 + threadIdx.x;
        if (i < OUT_F) g_bias[i] = bmu[i] + beps[i] * __expf(0.5f * blv[i]);
    }
}

// ============================================================
// GEMM: C[256,128] per CTA, 256 threads (8 warps = 4 x 2)
// warp tile 64 x 64, BK=32, 4-stage pipeline, refill 2 ahead,
// mainloop unrolled x4. Stage-free tracking via smem flag
// counters (release-add / acquire-spin) instead of mbarriers:
// fast path ~35 cyc vs ~90 for mbarrier.try_wait.
// ============================================================
__global__ void __launch_bounds__(THREADS, 1) gemm_kernel(float* __restrict__ out) {
    extern __shared__ char smem[];
    const uint32_t sb = smem_u32(smem);
    const int tid = threadIdx.x;
    const int wid = tid >> 5;
    const int lane = tid & 31;
    const int wm = wid >> 1;      // 0..3  (M, 64 rows)
    const int wn = wid & 1;       // 0..1  (N, 64 cols)
    const int gq = lane >> 2;
    const int tg = lane & 3;

    int pid = blockIdx.x;
    int grp = pid / (TILE_GROUP * NPN);
    int pin = pid % (TILE_GROUP * NPN);
    int pm  = grp * TILE_GROUP + (pin % TILE_GROUP);
    int pn  = pin / TILE_GROUP;
    const int m0 = pm * BM;
    const int n0 = pn * BN;
    const int m016 = m0 >> 4;
    const int n08  = n0 >> 3;

    // full[s] mbar at sb + s*8; read-done flag[s] (u32) at sb + 64 + s*4
    if (tid == 0) {
#pragma unroll
        for (int s = 0; s < STAGES; ++s) {
            mbar_init(sb + s * 8, 256);
            asm volatile("st.shared.u32 [%0], %1;" :: "r"(sb + 64 + s * 4), "r"(0u)
                         : "memory");
        }
    }
    __syncthreads();

    // ---- strength-reduced refill offsets ----
    uint32_t offA[8], offB[4];
#pragma unroll
    for (int t = 0; t < 8; ++t) {
        int ca = tid + t * THREADS;
        int r16l = ca >> 7;
        int inner = ca & 127;
        offA[t] = (uint32_t)(((((m016 + r16l) * NK8) + (inner >> 5)) * 32
                              + (inner & 31)) * 16);
    }
#pragma unroll
    for (int t = 0; t < 4; ++t) {
        int cb = tid + t * THREADS;
        int c8l = cb >> 6;
        int inner = cb & 63;
        offB[t] = (uint32_t)(((((n08 + c8l) * NK16) + (inner >> 5)) * 32
                              + (inner & 31)) * 16);
    }
    const char* gXb = (const char*)g_XP;
    const char* gWb = (const char*)g_WP;

    auto load_A = [&](uint32_t abase) {
#pragma unroll
        for (int t = 0; t < 8; ++t)
            cp16(abase + (uint32_t)(tid + t * THREADS) * 16u, gXb + offA[t]);
#pragma unroll
        for (int t = 0; t < 8; ++t) offA[t] += A_STEP;
    };
    auto load_B = [&](uint32_t bbase) {
#pragma unroll
        for (int t = 0; t < 4; ++t)
            cp16(bbase + (uint32_t)(tid + t * THREADS) * 16u, gWb + offB[t]);
#pragma unroll
        for (int t = 0; t < 4; ++t) offB[t] += B_STEP;
    };

    // prologue: load stages 0 and 1
    load_A(sb + SM_BUF0);
    load_B(sb + SM_BUF0 + SM_A_BYTES);
    cp_async_arrive(sb + 0);
    load_A(sb + SM_BUF0 + STAGE_BYTES);
    load_B(sb + SM_BUF0 + STAGE_BYTES + SM_A_BYTES);
    cp_async_arrive(sb + 8);

    float c[4][8][4];
#pragma unroll
    for (int mt = 0; mt < 4; ++mt)
#pragma unroll
        for (int nt = 0; nt < 8; ++nt)
#pragma unroll
            for (int j = 0; j < 4; ++j) c[mt][nt][j] = 0.0f;

    // T: flag target base; flag[s] counts 8 warp-arrivals per read-round.
    // Refill at kt (stage s2=(si+2)&3) needs reads of kt-2 done:
    // target = T for si in {0,1}, T+8 for si in {2,3}; T += 8 per ko block.
    uint32_t T = 0;

    for (int ko = 0; ko < NK; ko += 4) {
        const uint32_t op = (uint32_t)((ko >> 2) & 1);
#pragma unroll
        for (int si = 0; si < 4; ++si) {
            const int kt = ko + si;
            mbar_wait(sb + si * 8, op);               // full[si]

            const float4* sA = reinterpret_cast<const float4*>(
                smem + SM_BUF0 + (size_t)(si * STAGE_BYTES));
            const float4* sB = reinterpret_cast<const float4*>(
                smem + SM_BUF0 + (size_t)(si * STAGE_BYTES) + SM_A_BYTES);

            const int s2 = (si + 2) & 3;
            const uint32_t s2base = sb + SM_BUF0 + (uint32_t)(s2 * STAGE_BYTES);
            const bool more2 = (kt + 2 < NK);
            const uint32_t etarget = (si < 2) ? T : (T + 8u);

#pragma unroll
            for (int k16 = 0; k16 < 2; ++k16) {
                float4 af[4];
#pragma unroll
                for (int mt = 0; mt < 4; ++mt)
                    af[mt] = sA[(((wm * 4 + mt) * 4 + k16 * 2) * 32) + lane];
                float4 bf[8];
#pragma unroll
                for (int nt = 0; nt < 8; ++nt) {
                    bf[nt] = sB[(((wn * 8 + nt) * 2 + k16) * 32) + lane];
                    uint32_t b0 = __float_as_uint(bf[nt].x);
                    uint32_t b1 = __float_as_uint(bf[nt].y);
#pragma unroll
                    for (int mt = 0; mt < 4; ++mt) {
                        mma_tf32(c[mt][nt][0], c[mt][nt][1],
                                 c[mt][nt][2], c[mt][nt][3],
                                 __float_as_uint(af[mt].x), __float_as_uint(af[mt].y),
                                 __float_as_uint(af[mt].z), __float_as_uint(af[mt].w),
                                 b0, b1);
                    }
                }
#pragma unroll
                for (int mt = 0; mt < 4; ++mt)
                    af[mt] = sA[(((wm * 4 + mt) * 4 + k16 * 2 + 1) * 32) + lane];
#pragma unroll
                for (int nt = 0; nt < 8; ++nt) {
                    uint32_t b0 = __float_as_uint(bf[nt].z);
                    uint32_t b1 = __float_as_uint(bf[nt].w);
#pragma unroll
                    for (int mt = 0; mt < 4; ++mt) {
                        mma_tf32(c[mt][nt][0], c[mt][nt][1],
                                 c[mt][nt][2], c[mt][nt][3],
                                 __float_as_uint(af[mt].x), __float_as_uint(af[mt].y),
                                 __float_as_uint(af[mt].z), __float_as_uint(af[mt].w),
                                 b0, b1);
                    }
                }
                if (k16 == 0) {
                    if (more2) {
                        flag_wait(sb + 64 + s2 * 4, etarget);  // readers of kt-2 done
                        load_A(s2base);
                    }
                } else {
                    // all MMAs consuming stage si have issued -> reads complete
                    if (lane == 0) flag_add(sb + 64 + si * 4);
                    if (more2) {
                        load_B(s2base + SM_A_BYTES);
                        cp_async_arrive(sb + s2 * 8);          // full[s2]
                    }
                }
            }
        }
        T += 8u;
    }

    // ---- epilogue: bias + store ----
#pragma unroll
    for (int mt = 0; mt < 4; ++mt) {
        const int row0 = m0 + wm * 64 + mt * 16 + gq;
#pragma unroll
        for (int nt = 0; nt < 8; ++nt) {
            const int col = n0 + wn * 64 + nt * 8 + 2 * tg;
            const float2 bv = *reinterpret_cast<const float2*>(g_bias + col);
            float2 v0, v1;
            v0.x = c[mt][nt][0] + bv.x;
            v0.y = c[mt][nt][1] + bv.y;
            v1.x = c[mt][nt][2] + bv.x;
            v1.y = c[mt][nt][3] + bv.y;
            *reinterpret_cast<float2*>(out + (size_t)row0 * OUT_F + col) = v0;
            *reinterpret_cast<float2*>(out + (size_t)(row0 + 8) * OUT_F + col) = v1;
        }
    }
}

// ============================================================
// Launch
// ============================================================
extern "C" void kernel_launch(void* const* d_in, const int* in_sizes, int n_in,
                              void* d_out, int out_size) {
    const float* x    = (const float*)d_in[0];
    const float* wmu  = (const float*)d_in[1];
    const float* wlv  = (const float*)d_in[2];
    const float* bmu  = (const float*)d_in[3];
    const float* blv  = (const float*)d_in[4];
    const float* weps = (const float*)d_in[5];
    const float* beps = (const float*)d_in[6];
    float* out = (float*)d_out;

    prep_fused<<<PREP_BLOCKS, 256>>>(x, wmu, wlv, weps, bmu, blv, beps);

    cudaFuncSetAttribute(gemm_kernel,
                         cudaFuncAttributeMaxDynamicSharedMemorySize, SMEM_TOTAL);
    gemm_kernel<<<NPM * NPN, THREADS, SMEM_TOTAL>>>(out);
}